// round 1
// baseline (speedup 1.0000x reference)
#include <cuda_runtime.h>

// MLP3D_final: fused fp32 SIMT implementation.
// Per block: TM=64 points, 256 threads (8 row-groups x 32 col-groups, 8x8 reg tiles).
// Pipeline (all in one kernel, smem-resident activations):
//   embed (sincos + angle doubling) -> sE[64][65]
//   GEMM0: X  = E @ W0 + b0                      -> sX[64][256]
//   GEMM1: A1 = relu(X @ W1 + b1)                -> sA[64][256]
//   PART : for p in 0..3: relu(X[:,s:e] @ W1[s:e,s:e] + b1[s:e]) . Wc[p,s:e] + bc[p]
//          (only the diagonal 64x64 block of W1 matters due to double masking)
//   GEMM2: A2 = relu(A1 @ W2 + b2); occ = A2 . Wocc + bocc  (A2 never stored)
// Output layout assumed: d_out[0:N) = occ, d_out[N:5N) = part_class row-major [N,4].

#define THREADS 256
#define TM 64

// smem layout (floats)
#define SE_STRIDE 65
#define OFF_SE 0
#define OFF_SX (OFF_SE + 64 * SE_STRIDE)
#define OFF_SA (OFF_SX + 64 * 256)
#define OFF_SW (OFF_SA + 64 * 256)
#define SMEM_FLOATS (OFF_SW + 32 * 256)
#define SMEM_BYTES (SMEM_FLOATS * 4)

__device__ __forceinline__ void gemm_acc(
    const float* __restrict__ gW,   // [K,256] row-major global weights
    const float* sIn, int inStride, // [>=64 rows, stride] activations in smem
    int K,
    float* sW,                      // 32x256 staging buffer
    float acc[8][8],
    int trow, int tcol, int tid)
{
#pragma unroll
    for (int r = 0; r < 8; ++r)
#pragma unroll
        for (int c = 0; c < 8; ++c) acc[r][c] = 0.f;

    for (int k0 = 0; k0 < K; k0 += 32) {
        const int kt = (K - k0 < 32) ? (K - k0) : 32;
        __syncthreads();
        // stage weight k-tile (coalesced float4)
        const int n4 = kt * 64;
        for (int i = tid; i < n4; i += THREADS) {
            const int row = i >> 6, c4 = i & 63;
            ((float4*)sW)[i] = *(const float4*)(gW + (k0 + row) * 256 + c4 * 4);
        }
        __syncthreads();

        const float* xb = sIn + (trow * 8) * inStride + k0;
        const float* wb = sW + tcol * 8;
        if (kt == 32) {
#pragma unroll 4
            for (int kk = 0; kk < 32; ++kk) {
                float xv[8];
#pragma unroll
                for (int r = 0; r < 8; ++r) xv[r] = xb[r * inStride + kk];
                const float4 wa = *(const float4*)(wb + kk * 256);
                const float4 wc = *(const float4*)(wb + kk * 256 + 4);
                const float wv[8] = {wa.x, wa.y, wa.z, wa.w, wc.x, wc.y, wc.z, wc.w};
#pragma unroll
                for (int r = 0; r < 8; ++r)
#pragma unroll
                    for (int c = 0; c < 8; ++c)
                        acc[r][c] = fmaf(xv[r], wv[c], acc[r][c]);
            }
        } else {
            for (int kk = 0; kk < kt; ++kk) {
                float xv[8];
#pragma unroll
                for (int r = 0; r < 8; ++r) xv[r] = xb[r * inStride + kk];
                const float4 wa = *(const float4*)(wb + kk * 256);
                const float4 wc = *(const float4*)(wb + kk * 256 + 4);
                const float wv[8] = {wa.x, wa.y, wa.z, wa.w, wc.x, wc.y, wc.z, wc.w};
#pragma unroll
                for (int r = 0; r < 8; ++r)
#pragma unroll
                    for (int c = 0; c < 8; ++c)
                        acc[r][c] = fmaf(xv[r], wv[c], acc[r][c]);
            }
        }
    }
}

__global__ __launch_bounds__(THREADS)
void mlp3d_kernel(
    const float* __restrict__ coords,
    const float* __restrict__ W0, const float* __restrict__ b0,
    const float* __restrict__ W1, const float* __restrict__ b1,
    const float* __restrict__ W2, const float* __restrict__ b2,
    const float* __restrict__ Wocc, const float* __restrict__ bocc,
    const float* __restrict__ Wc, const float* __restrict__ bc,
    float* __restrict__ out_occ, float* __restrict__ out_cls, int npts)
{
    extern __shared__ float smem[];
    float* sE = smem + OFF_SE;
    float* sX = smem + OFF_SX;
    float* sA = smem + OFF_SA;
    float* sW = smem + OFF_SW;

    const int tid  = threadIdx.x;
    const int trow = tid >> 5;   // 0..7  -> rows trow*8..+8
    const int tcol = tid & 31;   // 0..31 -> cols tcol*8..+8
    const int nbase = blockIdx.x * TM;

    // ---- embedding: one thread per point (threads 0..63) ----
    if (tid < TM) {
        const int n = nbase + tid;
        float cd[3] = {0.f, 0.f, 0.f};
        if (n < npts) {
            cd[0] = coords[n * 3 + 0];
            cd[1] = coords[n * 3 + 1];
            cd[2] = coords[n * 3 + 2];
        }
        float* e = sE + tid * SE_STRIDE;
        e[63] = 0.f;
#pragma unroll
        for (int d = 0; d < 3; ++d) {
            e[d] = cd[d];
            float s, co;
            sincosf(cd[d], &s, &co);
#pragma unroll
            for (int f = 0; f < 10; ++f) {
                e[3 + f * 6 + d] = s;       // sin(2^f x_d)
                e[6 + f * 6 + d] = co;      // cos(2^f x_d)
                const float s2 = 2.f * s * co;
                const float c2 = fmaf(-2.f * s, s, 1.f);
                s = s2; co = c2;
            }
        }
    }

    float acc[8][8];

    // ---- GEMM0: X = E @ W0 + b0 (no activation) ----
    gemm_acc(W0, sE, SE_STRIDE, 63, sW, acc, trow, tcol, tid);
    {
        float bv[8];
#pragma unroll
        for (int c = 0; c < 8; ++c) bv[c] = b0[tcol * 8 + c];
#pragma unroll
        for (int r = 0; r < 8; ++r) {
            float4 v0 = {acc[r][0] + bv[0], acc[r][1] + bv[1], acc[r][2] + bv[2], acc[r][3] + bv[3]};
            float4 v1 = {acc[r][4] + bv[4], acc[r][5] + bv[5], acc[r][6] + bv[6], acc[r][7] + bv[7]};
            float* dst = sX + (trow * 8 + r) * 256 + tcol * 8;
            *(float4*)dst = v0;
            *(float4*)(dst + 4) = v1;
        }
    }

    // ---- GEMM1: A1 = relu(X @ W1 + b1) ----
    gemm_acc(W1, sX, 256, 256, sW, acc, trow, tcol, tid);
    {
        float bv[8];
#pragma unroll
        for (int c = 0; c < 8; ++c) bv[c] = b1[tcol * 8 + c];
#pragma unroll
        for (int r = 0; r < 8; ++r) {
            float4 v0 = {fmaxf(acc[r][0] + bv[0], 0.f), fmaxf(acc[r][1] + bv[1], 0.f),
                         fmaxf(acc[r][2] + bv[2], 0.f), fmaxf(acc[r][3] + bv[3], 0.f)};
            float4 v1 = {fmaxf(acc[r][4] + bv[4], 0.f), fmaxf(acc[r][5] + bv[5], 0.f),
                         fmaxf(acc[r][6] + bv[6], 0.f), fmaxf(acc[r][7] + bv[7], 0.f)};
            float* dst = sA + (trow * 8 + r) * 256 + tcol * 8;
            *(float4*)dst = v0;
            *(float4*)(dst + 4) = v1;
        }
    }

    // ---- PART branch: diagonal 64x64 blocks of W1, fused class heads ----
    {
        const int p = tcol >> 3;   // part id 0..3
        const int q = tcol & 7;    // col group within part
#pragma unroll
        for (int r = 0; r < 8; ++r)
#pragma unroll
            for (int c = 0; c < 8; ++c) acc[r][c] = 0.f;

        for (int k0 = 0; k0 < 64; k0 += 32) {
            __syncthreads();
            // stage gathered diag blocks: sW[row][c] = W1[(c/64)*64 + k0 + row][c]
            for (int i = tid; i < 32 * 64; i += THREADS) {
                const int row = i >> 6, c4 = i & 63;
                const int c = c4 * 4;
                const int pp = c >> 6;
                ((float4*)sW)[i] = *(const float4*)(W1 + (pp * 64 + k0 + row) * 256 + c);
            }
            __syncthreads();
            const float* xb = sX + (trow * 8) * 256 + p * 64 + k0;
            const float* wb = sW + tcol * 8;
#pragma unroll 4
            for (int kk = 0; kk < 32; ++kk) {
                float xv[8];
#pragma unroll
                for (int r = 0; r < 8; ++r) xv[r] = xb[r * 256 + kk];
                const float4 wa = *(const float4*)(wb + kk * 256);
                const float4 wc2 = *(const float4*)(wb + kk * 256 + 4);
                const float wv[8] = {wa.x, wa.y, wa.z, wa.w, wc2.x, wc2.y, wc2.z, wc2.w};
#pragma unroll
                for (int r = 0; r < 8; ++r)
#pragma unroll
                    for (int c = 0; c < 8; ++c)
                        acc[r][c] = fmaf(xv[r], wv[c], acc[r][c]);
            }
        }
        // epilogue: relu + class-head dot + reduce over 8 lanes of this part
        float bv[8], wv[8];
#pragma unroll
        for (int c = 0; c < 8; ++c) {
            const int j = p * 64 + q * 8 + c;
            bv[c] = b1[j];
            wv[c] = Wc[p * 256 + j];
        }
        float partial[8];
#pragma unroll
        for (int r = 0; r < 8; ++r) {
            float s = 0.f;
#pragma unroll
            for (int c = 0; c < 8; ++c)
                s = fmaf(fmaxf(acc[r][c] + bv[c], 0.f), wv[c], s);
            partial[r] = s;
        }
#pragma unroll
        for (int off = 4; off > 0; off >>= 1)
#pragma unroll
            for (int r = 0; r < 8; ++r)
                partial[r] += __shfl_down_sync(0xffffffffu, partial[r], off, 8);
        if (q == 0) {
            const float bcp = bc[p];
#pragma unroll
            for (int r = 0; r < 8; ++r) {
                const int n = nbase + trow * 8 + r;
                if (n < npts) out_cls[n * 4 + p] = partial[r] + bcp;
            }
        }
    }

    // ---- GEMM2 + occ head (A2 never stored) ----
    gemm_acc(W2, sA, 256, 256, sW, acc, trow, tcol, tid);
    {
        float bv[8], wv[8];
#pragma unroll
        for (int c = 0; c < 8; ++c) {
            const int j = tcol * 8 + c;
            bv[c] = b2[j];
            wv[c] = Wocc[j];
        }
        float po[8];
#pragma unroll
        for (int r = 0; r < 8; ++r) {
            float s = 0.f;
#pragma unroll
            for (int c = 0; c < 8; ++c)
                s = fmaf(fmaxf(acc[r][c] + bv[c], 0.f), wv[c], s);
            po[r] = s;
        }
#pragma unroll
        for (int off = 16; off > 0; off >>= 1)
#pragma unroll
            for (int r = 0; r < 8; ++r)
                po[r] += __shfl_down_sync(0xffffffffu, po[r], off, 32);
        if (tcol == 0) {
            const float bo = bocc[0];
#pragma unroll
            for (int r = 0; r < 8; ++r) {
                const int n = nbase + trow * 8 + r;
                if (n < npts) out_occ[n] = po[r] + bo;
            }
        }
    }
}

extern "C" void kernel_launch(void* const* d_in, const int* in_sizes, int n_in,
                              void* d_out, int out_size) {
    const float* coords = (const float*)d_in[0];
    const float* W0   = (const float*)d_in[1];
    const float* b0   = (const float*)d_in[2];
    const float* W1   = (const float*)d_in[3];
    const float* b1   = (const float*)d_in[4];
    const float* W2   = (const float*)d_in[5];
    const float* b2   = (const float*)d_in[6];
    const float* Wocc = (const float*)d_in[7];
    const float* bocc = (const float*)d_in[8];
    const float* Wc   = (const float*)d_in[9];
    const float* bc   = (const float*)d_in[10];

    const int npts = in_sizes[0] / 3;
    float* out_occ = (float*)d_out;          // [npts]
    float* out_cls = (float*)d_out + npts;   // [npts, 4]

    cudaFuncSetAttribute(mlp3d_kernel,
                         cudaFuncAttributeMaxDynamicSharedMemorySize, SMEM_BYTES);

    const int blocks = (npts + TM - 1) / TM;
    mlp3d_kernel<<<blocks, THREADS, SMEM_BYTES>>>(
        coords, W0, b0, W1, b1, W2, b2, Wocc, bocc, Wc, bc,
        out_occ, out_cls, npts);
}

// round 3
// speedup vs baseline: 8.7147x; 8.7147x over previous
#include <cuda_runtime.h>
#include <cuda_fp16.h>
#include <cstdint>

// MLP3D_final — mma.sync (HMMA m16n8k16, f16 in / f32 accum) implementation.
// Harness ptxas targets plain sm_103 (no 'a' feature) -> tcgen05 unavailable;
// baseline tensor-core path via mma.sync + ldmatrix + cp.async instead.
//
// Per block: 128 points as 2 subtiles of 64 rows; 256 threads = 8 warps
// arranged 2 (row groups of 32) x 4 (col groups of 64) over a 64x256 GEMM tile.
// Phases (per block):
//   stage W0t+W1bdT (cp.async) || embed -> sE f16 (stride 72)
//   P0: X  = E @ W0t^T + b0            (K=64)   -> f16 sX (stride 264)
//   P1: part p: relu(X[:,p*64:] @ W1diag^T + b1) . Wc  -> out_cls (K=64/warp)
//   stage W1t
//   P2: A1 = relu(X @ W1t^T + b1)      (K=256)  -> f16 sX (in place)
//   stage W2t
//   P3: occ = relu(A1 @ W2t^T + b2) . Wocc + bocc      (K=256)
// Weights pre-transposed to n-major f16 images with padded stride by prep kernel.

#define THREADS 256

// strides in f16 elements
#define SA 264   // activation tiles (K=256 + 8 pad)
#define SE 72    // embedding tile   (K=64 + 8 pad)
#define SB 264   // big weight images
#define SW 72    // small weight images (k=64)

// smem byte offsets
#define OFF_W0T 0
#define OFF_W1BD 36864
#define OFF_E   73728
#define E_TILE  9216
#define OFF_X   135168
#define X_TILE  33792
#define OFF_PAR 202752
#define OFF_OCC 207904
#define SMEM_BYTES 209952

// param vector layout (floats)
#define PB0 0
#define PB1 256
#define PB2 512
#define PWC 768
#define PWOCC 1024
#define PBC 1280
#define PBOCC 1284
#define NPAR 1285

__device__ __align__(16) unsigned char gW0t[256 * SW * 2];
__device__ __align__(16) unsigned char gW1bd[256 * SW * 2];
__device__ __align__(16) unsigned char gW1t[256 * SB * 2];
__device__ __align__(16) unsigned char gW2t[256 * SB * 2];
__device__ float gParams[NPAR];

// ---------------- PTX helpers (all baseline sm_80+ features) ----------------
__device__ __forceinline__ uint32_t smem_u32(const void* p) {
    uint32_t a;
    asm("{ .reg .u64 t; cvta.to.shared.u64 t, %1; cvt.u32.u64 %0, t; }" : "=r"(a) : "l"(p));
    return a;
}
__device__ __forceinline__ void ldmx4(uint32_t* r, uint32_t a) {
    asm volatile("ldmatrix.sync.aligned.m8n8.x4.shared.b16 {%0,%1,%2,%3}, [%4];"
                 : "=r"(r[0]), "=r"(r[1]), "=r"(r[2]), "=r"(r[3]) : "r"(a));
}
__device__ __forceinline__ void mma16816(float* d, const uint32_t* a, uint32_t b0, uint32_t b1) {
    asm volatile(
        "mma.sync.aligned.m16n8k16.row.col.f32.f16.f16.f32 "
        "{%0,%1,%2,%3}, {%4,%5,%6,%7}, {%8,%9}, {%0,%1,%2,%3};"
        : "+f"(d[0]), "+f"(d[1]), "+f"(d[2]), "+f"(d[3])
        : "r"(a[0]), "r"(a[1]), "r"(a[2]), "r"(a[3]), "r"(b0), "r"(b1));
}
__device__ __forceinline__ void cp16(uint32_t dst, const void* src) {
    asm volatile("cp.async.cg.shared.global [%0], [%1], 16;" :: "r"(dst), "l"(src));
}
#define CP_COMMIT() asm volatile("cp.async.commit_group;" ::: "memory")
#define CP_WAIT0()  asm volatile("cp.async.wait_group 0;" ::: "memory")

// ---------------- prep kernel: transpose + f16 padded images ----------------
__global__ void prep_kernel(
    const float* __restrict__ W0, const float* __restrict__ b0,
    const float* __restrict__ W1, const float* __restrict__ b1,
    const float* __restrict__ W2, const float* __restrict__ b2,
    const float* __restrict__ Wocc, const float* __restrict__ bocc,
    const float* __restrict__ Wc, const float* __restrict__ bc)
{
    const int idx = blockIdx.x * blockDim.x + threadIdx.x;
    const int stride = gridDim.x * blockDim.x;
    // items: n fastest (coalesced src reads); t selects segment/k-pair
    for (int i = idx; i < 256 * 320; i += stride) {
        const int n = i & 255;
        const int t = i >> 8;
        if (t < 32) {                                   // W0t: [n][k<64]
            const int k = t * 2;
            const float v0 = (k < 63) ? W0[k * 256 + n] : 0.f;
            const float v1 = (k + 1 < 63) ? W0[(k + 1) * 256 + n] : 0.f;
            __half2 h = __floats2half2_rn(v0, v1);
            *(uint32_t*)(gW0t + (n * SW + k) * 2) = *(uint32_t*)&h;
        } else if (t < 64) {                            // W1bdT: diag blocks
            const int k = (t - 32) * 2;
            const int base = (n >> 6) * 64;
            __half2 h = __floats2half2_rn(W1[(base + k) * 256 + n],
                                          W1[(base + k + 1) * 256 + n]);
            *(uint32_t*)(gW1bd + (n * SW + k) * 2) = *(uint32_t*)&h;
        } else if (t < 192) {                           // W1t
            const int k = (t - 64) * 2;
            __half2 h = __floats2half2_rn(W1[k * 256 + n], W1[(k + 1) * 256 + n]);
            *(uint32_t*)(gW1t + (n * SB + k) * 2) = *(uint32_t*)&h;
        } else {                                        // W2t
            const int k = (t - 192) * 2;
            __half2 h = __floats2half2_rn(W2[k * 256 + n], W2[(k + 1) * 256 + n]);
            *(uint32_t*)(gW2t + (n * SB + k) * 2) = *(uint32_t*)&h;
        }
    }
    if (idx < 256) {
        gParams[PB0 + idx] = b0[idx];
        gParams[PB1 + idx] = b1[idx];
        gParams[PB2 + idx] = b2[idx];
        gParams[PWC + idx] = Wc[(idx >> 6) * 256 + idx];
        gParams[PWOCC + idx] = Wocc[idx];
    } else if (idx < 260) {
        gParams[PBC + idx - 256] = bc[idx - 256];
    } else if (idx == 260) {
        gParams[PBOCC] = bocc[0];
    }
}

// ---------------- warp GEMM: 32x64 tile, k-step 16 ----------------
template <int KSTEPS>
__device__ __forceinline__ void run_gemm(float (&acc)[2][8][4],
                                         uint32_t aAddr, uint32_t aOff16,
                                         uint32_t bAddr, uint32_t bJ)
{
#pragma unroll
    for (int rt = 0; rt < 2; ++rt)
#pragma unroll
        for (int ct = 0; ct < 8; ++ct)
#pragma unroll
            for (int q = 0; q < 4; ++q) acc[rt][ct][q] = 0.f;

#pragma unroll 4
    for (int ks = 0; ks < KSTEPS; ++ks) {
        uint32_t a0[4], a1[4], b[4][4];
        ldmx4(a0, aAddr);
        ldmx4(a1, aAddr + aOff16);
#pragma unroll
        for (int j = 0; j < 4; ++j) ldmx4(b[j], bAddr + j * bJ);
        aAddr += 32;  // 16 halves
        bAddr += 32;
#pragma unroll
        for (int j = 0; j < 4; ++j) {
            mma16816(acc[0][2 * j],     a0, b[j][0], b[j][1]);
            mma16816(acc[0][2 * j + 1], a0, b[j][2], b[j][3]);
            mma16816(acc[1][2 * j],     a1, b[j][0], b[j][1]);
            mma16816(acc[1][2 * j + 1], a1, b[j][2], b[j][3]);
        }
    }
}

// ---------------- main kernel ----------------
__global__ __launch_bounds__(THREADS, 1)
void mlp3d_mma(const float* __restrict__ coords,
               float* __restrict__ out_occ, float* __restrict__ out_cls, int npts)
{
    extern __shared__ unsigned char sm[];
    const uint32_t sb = smem_u32(sm);
    float* sPar = (float*)(sm + OFF_PAR);
    float* sOcc = (float*)(sm + OFF_OCC);

    const int tid = threadIdx.x;
    const int lane = tid & 31, wid = tid >> 5;
    const int wr = wid >> 2, wc = wid & 3;
    const int gid = lane >> 2, tid4 = lane & 3;
    const int nbase = blockIdx.x * 128;

    // ---- stage small weights (async) ----
    for (int i = tid * 16; i < 36864; i += THREADS * 16) {
        cp16(sb + OFF_W0T + i, gW0t + i);
        cp16(sb + OFF_W1BD + i, gW1bd + i);
    }
    CP_COMMIT();

    // ---- embed (threads 0-127) || params load (threads 128-255) ----
    if (tid < 128) {
        const int t = tid >> 6, row = tid & 63;
        const int n = nbase + t * 64 + row;
        float c3[3] = {0.f, 0.f, 0.f};
        if (n < npts) {
            c3[0] = coords[n * 3 + 0];
            c3[1] = coords[n * 3 + 1];
            c3[2] = coords[n * 3 + 2];
        }
        __half* e = (__half*)(sm + OFF_E + t * E_TILE) + row * SE;
        e[63] = __float2half_rn(0.f);
#pragma unroll
        for (int d = 0; d < 3; ++d) {
            e[d] = __float2half_rn(c3[d]);
            float s, co;
            sincosf(c3[d], &s, &co);
#pragma unroll
            for (int f = 0; f < 10; ++f) {
                e[3 + f * 6 + d] = __float2half_rn(s);
                e[6 + f * 6 + d] = __float2half_rn(co);
                const float s2 = 2.f * s * co;
                const float c2 = fmaf(-2.f * s, s, 1.f);
                s = s2; co = c2;
            }
        }
    } else {
        for (int i = tid - 128; i < NPAR; i += 128) sPar[i] = gParams[i];
    }
    CP_WAIT0();
    __syncthreads();

    // per-lane ldmatrix address components
    const int aRow = (lane & 7) + ((lane >> 3) & 1) * 8;
    const int aK   = ((lane >> 4) & 1) * 8;
    const int bRow = (lane & 7) + ((lane >> 4) & 1) * 8;
    const int bK   = ((lane >> 3) & 1) * 8;
    const uint32_t bAddrW0 = sb + OFF_W0T + ((wc * 64 + bRow) * SW + bK) * 2;
    const uint32_t bAddrBD = sb + OFF_W1BD + ((wc * 64 + bRow) * SW + bK) * 2;
    const uint32_t bAddrBig = sb + ((wc * 64 + bRow) * SB + bK) * 2;  // W1t/W2t at offset 0
    const uint32_t bJs = 16 * SW * 2, bJb = 16 * SB * 2;

    float acc[2][8][4];

    // ================= P0: X = E @ W0t^T + b0 =================
    for (int t = 0; t < 2; ++t) {
        const uint32_t aA = sb + OFF_E + t * E_TILE + ((wr * 32 + aRow) * SE + aK) * 2;
        run_gemm<4>(acc, aA, 16 * SE * 2, bAddrW0, bJs);
        unsigned char* xB = sm + OFF_X + t * X_TILE;
#pragma unroll
        for (int rt = 0; rt < 2; ++rt) {
            const int r0 = wr * 32 + rt * 16 + gid;
#pragma unroll
            for (int ct = 0; ct < 8; ++ct) {
                const int c = wc * 64 + ct * 8 + tid4 * 2;
                const float bv0 = sPar[PB0 + c], bv1 = sPar[PB0 + c + 1];
                __half2 h0 = __floats2half2_rn(acc[rt][ct][0] + bv0, acc[rt][ct][1] + bv1);
                __half2 h1 = __floats2half2_rn(acc[rt][ct][2] + bv0, acc[rt][ct][3] + bv1);
                *(uint32_t*)(xB + (r0 * SA + c) * 2) = *(uint32_t*)&h0;
                *(uint32_t*)(xB + ((r0 + 8) * SA + c) * 2) = *(uint32_t*)&h1;
            }
        }
    }
    __syncthreads();

    // ================= P1: part branches + class heads =================
    for (int t = 0; t < 2; ++t) {
        const uint32_t aA = sb + OFF_X + t * X_TILE +
                            ((wr * 32 + aRow) * SA + aK + wc * 64) * 2;
        run_gemm<4>(acc, aA, 16 * SA * 2, bAddrBD, bJs);
        const int p = wc;
#pragma unroll
        for (int rt = 0; rt < 2; ++rt) {
            float s0 = 0.f, s1 = 0.f;
#pragma unroll
            for (int ct = 0; ct < 8; ++ct) {
                const int c = wc * 64 + ct * 8 + tid4 * 2;
                const float b0v = sPar[PB1 + c], b1v = sPar[PB1 + c + 1];
                const float w0v = sPar[PWC + c], w1v = sPar[PWC + c + 1];
                s0 = fmaf(fmaxf(acc[rt][ct][0] + b0v, 0.f), w0v, s0);
                s0 = fmaf(fmaxf(acc[rt][ct][1] + b1v, 0.f), w1v, s0);
                s1 = fmaf(fmaxf(acc[rt][ct][2] + b0v, 0.f), w0v, s1);
                s1 = fmaf(fmaxf(acc[rt][ct][3] + b1v, 0.f), w1v, s1);
            }
            s0 += __shfl_xor_sync(0xffffffffu, s0, 1);
            s0 += __shfl_xor_sync(0xffffffffu, s0, 2);
            s1 += __shfl_xor_sync(0xffffffffu, s1, 1);
            s1 += __shfl_xor_sync(0xffffffffu, s1, 2);
            if (tid4 == 0) {
                const float bcp = sPar[PBC + p];
                int n = nbase + t * 64 + wr * 32 + rt * 16 + gid;
                if (n < npts) out_cls[n * 4 + p] = s0 + bcp;
                n += 8;
                if (n < npts) out_cls[n * 4 + p] = s1 + bcp;
            }
        }
    }
    __syncthreads();

    // ---- stage W1t (full buffer) ----
    for (int i = tid * 16; i < 256 * SB * 2; i += THREADS * 16) cp16(sb + i, gW1t + i);
    CP_COMMIT();
    CP_WAIT0();
    __syncthreads();

    // ================= P2: A1 = relu(X @ W1t^T + b1) (in place) =================
    for (int t = 0; t < 2; ++t) {
        const uint32_t aA = sb + OFF_X + t * X_TILE + ((wr * 32 + aRow) * SA + aK) * 2;
        run_gemm<16>(acc, aA, 16 * SA * 2, bAddrBig, bJb);
        __syncthreads();  // all reads of sX(t) complete before overwrite
        unsigned char* xB = sm + OFF_X + t * X_TILE;
#pragma unroll
        for (int rt = 0; rt < 2; ++rt) {
            const int r0 = wr * 32 + rt * 16 + gid;
#pragma unroll
            for (int ct = 0; ct < 8; ++ct) {
                const int c = wc * 64 + ct * 8 + tid4 * 2;
                const float bv0 = sPar[PB1 + c], bv1 = sPar[PB1 + c + 1];
                __half2 h0 = __floats2half2_rn(fmaxf(acc[rt][ct][0] + bv0, 0.f),
                                               fmaxf(acc[rt][ct][1] + bv1, 0.f));
                __half2 h1 = __floats2half2_rn(fmaxf(acc[rt][ct][2] + bv0, 0.f),
                                               fmaxf(acc[rt][ct][3] + bv1, 0.f));
                *(uint32_t*)(xB + (r0 * SA + c) * 2) = *(uint32_t*)&h0;
                *(uint32_t*)(xB + ((r0 + 8) * SA + c) * 2) = *(uint32_t*)&h1;
            }
        }
    }
    __syncthreads();

    // ---- stage W2t ----
    for (int i = tid * 16; i < 256 * SB * 2; i += THREADS * 16) cp16(sb + i, gW2t + i);
    CP_COMMIT();
    CP_WAIT0();
    __syncthreads();

    // ================= P3: occ = relu(A1 @ W2t^T + b2) . Wocc =================
    for (int t = 0; t < 2; ++t) {
        const uint32_t aA = sb + OFF_X + t * X_TILE + ((wr * 32 + aRow) * SA + aK) * 2;
        run_gemm<16>(acc, aA, 16 * SA * 2, bAddrBig, bJb);
#pragma unroll
        for (int rt = 0; rt < 2; ++rt) {
            float s0 = 0.f, s1 = 0.f;
#pragma unroll
            for (int ct = 0; ct < 8; ++ct) {
                const int c = wc * 64 + ct * 8 + tid4 * 2;
                const float b0v = sPar[PB2 + c], b1v = sPar[PB2 + c + 1];
                const float w0v = sPar[PWOCC + c], w1v = sPar[PWOCC + c + 1];
                s0 = fmaf(fmaxf(acc[rt][ct][0] + b0v, 0.f), w0v, s0);
                s0 = fmaf(fmaxf(acc[rt][ct][1] + b1v, 0.f), w1v, s0);
                s1 = fmaf(fmaxf(acc[rt][ct][2] + b0v, 0.f), w0v, s1);
                s1 = fmaf(fmaxf(acc[rt][ct][3] + b1v, 0.f), w1v, s1);
            }
            s0 += __shfl_xor_sync(0xffffffffu, s0, 1);
            s0 += __shfl_xor_sync(0xffffffffu, s0, 2);
            s1 += __shfl_xor_sync(0xffffffffu, s1, 1);
            s1 += __shfl_xor_sync(0xffffffffu, s1, 2);
            if (tid4 == 0) {
                const int r = t * 64 + wr * 32 + rt * 16 + gid;
                sOcc[r * 4 + wc] = s0;
                sOcc[(r + 8) * 4 + wc] = s1;
            }
        }
    }
    __syncthreads();
    if (tid < 128) {
        const float v = sOcc[tid * 4] + sOcc[tid * 4 + 1] + sOcc[tid * 4 + 2] +
                        sOcc[tid * 4 + 3] + sPar[PBOCC];
        const int n = nbase + tid;
        if (n < npts) out_occ[n] = v;
    }
}

// ---------------- launch ----------------
extern "C" void kernel_launch(void* const* d_in, const int* in_sizes, int n_in,
                              void* d_out, int out_size) {
    const float* coords = (const float*)d_in[0];
    const float* W0   = (const float*)d_in[1];
    const float* b0   = (const float*)d_in[2];
    const float* W1   = (const float*)d_in[3];
    const float* b1   = (const float*)d_in[4];
    const float* W2   = (const float*)d_in[5];
    const float* b2   = (const float*)d_in[6];
    const float* Wocc = (const float*)d_in[7];
    const float* bocc = (const float*)d_in[8];
    const float* Wc   = (const float*)d_in[9];
    const float* bc   = (const float*)d_in[10];

    const int npts = in_sizes[0] / 3;
    float* out_occ = (float*)d_out;
    float* out_cls = (float*)d_out + npts;

    prep_kernel<<<320, 256>>>(W0, b0, W1, b1, W2, b2, Wocc, bocc, Wc, bc);

    cudaFuncSetAttribute(mlp3d_mma, cudaFuncAttributeMaxDynamicSharedMemorySize, SMEM_BYTES);
    const int blocks = (npts + 127) / 128;
    mlp3d_mma<<<blocks, THREADS, SMEM_BYTES>>>(coords, out_occ, out_cls, npts);
}